// round 3
// baseline (speedup 1.0000x reference)
#include <cuda_runtime.h>

// out[r] = dot(x[r], w_avg) + b_avg   (mean of linear == linear of mean)
//
// Persistent grid-stride kernel: 592 CTAs (4/SM x 148). Param reduction
// (W[10,1,10], b[10] -> smem coef[11]) happens once per CTA, then each
// thread streams 4 rows per iteration: 10 x float4 loads (160B, MLP=10),
// one float4 store. All x/out traffic uses streaming hints (single-use).

__global__ __launch_bounds__(256) void forest_persist_kernel(
    const float4* __restrict__ x4,   // x as float4; 10 per row-quad
    const float*  __restrict__ W,    // [10, 1, 10]
    const float*  __restrict__ b,    // [10, 1]
    float4* __restrict__ out4,       // out as float4; 1 per row-quad
    int nquads) {
    __shared__ float sc[11];
    if (threadIdx.x < 11) {
        float s = 0.f;
        if (threadIdx.x < 10) {
#pragma unroll
            for (int e = 0; e < 10; ++e) s += W[e * 10 + threadIdx.x];
        } else {
#pragma unroll
            for (int e = 0; e < 10; ++e) s += b[e];
        }
        sc[threadIdx.x] = s * 0.1f;
    }
    __syncthreads();

    const float c0 = sc[0], c1 = sc[1], c2 = sc[2], c3 = sc[3], c4 = sc[4];
    const float c5 = sc[5], c6 = sc[6], c7 = sc[7], c8 = sc[8], c9 = sc[9];
    const float bias = sc[10];

    const int stride = gridDim.x * blockDim.x;
    for (int t = blockIdx.x * blockDim.x + threadIdx.x; t < nquads; t += stride) {
        const float4* p = x4 + (size_t)t * 10;
        float4 v0 = __ldcs(p + 0);
        float4 v1 = __ldcs(p + 1);
        float4 v2 = __ldcs(p + 2);
        float4 v3 = __ldcs(p + 3);
        float4 v4 = __ldcs(p + 4);
        float4 v5 = __ldcs(p + 5);
        float4 v6 = __ldcs(p + 6);
        float4 v7 = __ldcs(p + 7);
        float4 v8 = __ldcs(p + 8);
        float4 v9 = __ldcs(p + 9);

        // Row 0: v0.xyzw v1.xyzw v2.xy
        float r0 = v0.x * c0;
        r0 = fmaf(v0.y, c1, r0); r0 = fmaf(v0.z, c2, r0);
        r0 = fmaf(v0.w, c3, r0); r0 = fmaf(v1.x, c4, r0);
        r0 = fmaf(v1.y, c5, r0); r0 = fmaf(v1.z, c6, r0);
        r0 = fmaf(v1.w, c7, r0); r0 = fmaf(v2.x, c8, r0);
        r0 = fmaf(v2.y, c9, r0);

        // Row 1: v2.zw v3.xyzw v4.xyzw
        float r1 = v2.z * c0;
        r1 = fmaf(v2.w, c1, r1); r1 = fmaf(v3.x, c2, r1);
        r1 = fmaf(v3.y, c3, r1); r1 = fmaf(v3.z, c4, r1);
        r1 = fmaf(v3.w, c5, r1); r1 = fmaf(v4.x, c6, r1);
        r1 = fmaf(v4.y, c7, r1); r1 = fmaf(v4.z, c8, r1);
        r1 = fmaf(v4.w, c9, r1);

        // Row 2: v5.xyzw v6.xyzw v7.xy
        float r2 = v5.x * c0;
        r2 = fmaf(v5.y, c1, r2); r2 = fmaf(v5.z, c2, r2);
        r2 = fmaf(v5.w, c3, r2); r2 = fmaf(v6.x, c4, r2);
        r2 = fmaf(v6.y, c5, r2); r2 = fmaf(v6.z, c6, r2);
        r2 = fmaf(v6.w, c7, r2); r2 = fmaf(v7.x, c8, r2);
        r2 = fmaf(v7.y, c9, r2);

        // Row 3: v7.zw v8.xyzw v9.xyzw
        float r3 = v7.z * c0;
        r3 = fmaf(v7.w, c1, r3); r3 = fmaf(v8.x, c2, r3);
        r3 = fmaf(v8.y, c3, r3); r3 = fmaf(v8.z, c4, r3);
        r3 = fmaf(v8.w, c5, r3); r3 = fmaf(v9.x, c6, r3);
        r3 = fmaf(v9.y, c7, r3); r3 = fmaf(v9.z, c8, r3);
        r3 = fmaf(v9.w, c9, r3);

        __stcs(out4 + t,
               make_float4(r0 + bias, r1 + bias, r2 + bias, r3 + bias));
    }
}

extern "C" void kernel_launch(void* const* d_in, const int* in_sizes, int n_in,
                              void* d_out, int out_size) {
    const float* x = (const float*)d_in[0];   // [B, 10]
    const float* W = (const float*)d_in[1];   // [10, 1, 10]
    const float* b = (const float*)d_in[2];   // [10, 1]

    int B = in_sizes[0] / 10;                 // 4,000,000
    int nquads = B / 4;                       // 1,000,000 (B divisible by 4)

    int threads = 256;
    int blocks = 592;                          // 4 CTAs/SM x 148 SMs
    int needed = (nquads + threads - 1) / threads;
    if (blocks > needed) blocks = needed;

    forest_persist_kernel<<<blocks, threads>>>(
        (const float4*)x, W, b, (float4*)d_out, nquads);
}

// round 4
// speedup vs baseline: 1.0396x; 1.0396x over previous
#include <cuda_runtime.h>

// out[r] = dot(x[r], w_avg) + b_avg   (mean of linear == linear of mean)
//
// Single fused kernel, BARRIER-FREE prologue: each warp independently reduces
// W[10,1,10], b[10] (440B, L1-resident after first wave) and broadcasts the 11
// coefficients via shuffles. No __syncthreads -> warps start streaming
// immediately. Body: one thread per ROW PAIR (80B = 5 x float4, 16B aligned),
// full grid (8 CTAs/SM residency), streaming cache hints on x and out.

__global__ __launch_bounds__(256) void forest_warp_kernel(
    const float4* __restrict__ x4,   // x as float4; 5 per row-pair
    const float*  __restrict__ W,    // [10, 1, 10]
    const float*  __restrict__ b,    // [10, 1]
    float2* __restrict__ out2,       // out as float2; 1 per row-pair
    int npairs) {
    const int lane = threadIdx.x & 31;

    // Per-warp coefficient reduction (lanes 0..9: w_avg[j], lane 10: b_avg).
    float s = 0.f;
    if (lane < 10) {
#pragma unroll
        for (int e = 0; e < 10; ++e) s += __ldg(W + e * 10 + lane);
    } else if (lane == 10) {
#pragma unroll
        for (int e = 0; e < 10; ++e) s += __ldg(b + e);
    }
    s *= 0.1f;

    const unsigned m = 0xFFFFFFFFu;
    const float c0 = __shfl_sync(m, s, 0);
    const float c1 = __shfl_sync(m, s, 1);
    const float c2 = __shfl_sync(m, s, 2);
    const float c3 = __shfl_sync(m, s, 3);
    const float c4 = __shfl_sync(m, s, 4);
    const float c5 = __shfl_sync(m, s, 5);
    const float c6 = __shfl_sync(m, s, 6);
    const float c7 = __shfl_sync(m, s, 7);
    const float c8 = __shfl_sync(m, s, 8);
    const float c9 = __shfl_sync(m, s, 9);
    const float bias = __shfl_sync(m, s, 10);

    int t = blockIdx.x * blockDim.x + threadIdx.x;
    if (t >= npairs) return;

    const float4* p = x4 + (size_t)t * 5;
    float4 v0 = __ldcs(p + 0);
    float4 v1 = __ldcs(p + 1);
    float4 v2 = __ldcs(p + 2);
    float4 v3 = __ldcs(p + 3);
    float4 v4 = __ldcs(p + 4);

    // Row 0 = {v0.xyzw, v1.xyzw, v2.xy}
    float r0 = v0.x * c0;
    r0 = fmaf(v0.y, c1, r0);
    r0 = fmaf(v0.z, c2, r0);
    r0 = fmaf(v0.w, c3, r0);
    r0 = fmaf(v1.x, c4, r0);
    r0 = fmaf(v1.y, c5, r0);
    r0 = fmaf(v1.z, c6, r0);
    r0 = fmaf(v1.w, c7, r0);
    r0 = fmaf(v2.x, c8, r0);
    r0 = fmaf(v2.y, c9, r0);

    // Row 1 = {v2.zw, v3.xyzw, v4.xyzw}
    float r1 = v2.z * c0;
    r1 = fmaf(v2.w, c1, r1);
    r1 = fmaf(v3.x, c2, r1);
    r1 = fmaf(v3.y, c3, r1);
    r1 = fmaf(v3.z, c4, r1);
    r1 = fmaf(v3.w, c5, r1);
    r1 = fmaf(v4.x, c6, r1);
    r1 = fmaf(v4.y, c7, r1);
    r1 = fmaf(v4.z, c8, r1);
    r1 = fmaf(v4.w, c9, r1);

    __stcs(out2 + t, make_float2(r0 + bias, r1 + bias));
}

extern "C" void kernel_launch(void* const* d_in, const int* in_sizes, int n_in,
                              void* d_out, int out_size) {
    const float* x = (const float*)d_in[0];   // [B, 10]
    const float* W = (const float*)d_in[1];   // [10, 1, 10]
    const float* b = (const float*)d_in[2];   // [10, 1]

    int B = in_sizes[0] / 10;                 // 4,000,000
    int npairs = B / 2;                       // B is even

    int threads = 256;
    int blocks = (npairs + threads - 1) / threads;
    forest_warp_kernel<<<blocks, threads>>>(
        (const float4*)x, W, b, (float2*)d_out, npairs);
}

// round 5
// speedup vs baseline: 1.1257x; 1.0828x over previous
#include <cuda_runtime.h>

// out[r] = dot(x[r], w_avg) + b_avg   (mean of linear == linear of mean)
//
// Single fused kernel with LATENCY-HIDDEN prologue:
//   1. every thread FIRST issues its 5 x float4 loads (DRAM, ~600cyc)
//   2. threads 0..10 then reduce W[10,1,10], b[10] -> smem coef[11]
//   3. __syncthreads (deferred-blocking BAR absorbs into x-load latency)
//   4. LDS coefs, 20 FMAs, predicated float2 store
// Body shape = R1 (best measured: 29.2us, DRAM 74%): full grid, 2 rows/thread
// (80B = 5 x float4, 16B aligned), streaming hints on x and out.

__global__ __launch_bounds__(256) void forest_hidden_kernel(
    const float4* __restrict__ x4,   // x as float4; 5 per row-pair
    const float*  __restrict__ W,    // [10, 1, 10]
    const float*  __restrict__ b,    // [10, 1]
    float2* __restrict__ out2,       // out as float2; 1 per row-pair
    int npairs) {
    __shared__ float sc[11];

    const int t = blockIdx.x * blockDim.x + threadIdx.x;
    const bool active = (t < npairs);
    const int tc = active ? t : (npairs - 1);   // clamped: tail lanes re-load last pair

    // ---- 1. x loads first: independent of everything, go out immediately ----
    const float4* p = x4 + (size_t)tc * 5;
    float4 v0 = __ldcs(p + 0);
    float4 v1 = __ldcs(p + 1);
    float4 v2 = __ldcs(p + 2);
    float4 v3 = __ldcs(p + 3);
    float4 v4 = __ldcs(p + 4);

    // ---- 2. param reduction by 11 threads (L1/L2-hit, overlaps x latency) ----
    if (threadIdx.x < 11) {
        float s = 0.f;
        if (threadIdx.x < 10) {
#pragma unroll
            for (int e = 0; e < 10; ++e) s += __ldg(W + e * 10 + threadIdx.x);
        } else {
#pragma unroll
            for (int e = 0; e < 10; ++e) s += __ldg(b + e);
        }
        sc[threadIdx.x] = s * 0.1f;
    }
    // ---- 3. deferred-blocking barrier: x loads already in flight ----
    __syncthreads();

    const float c0 = sc[0], c1 = sc[1], c2 = sc[2], c3 = sc[3], c4 = sc[4];
    const float c5 = sc[5], c6 = sc[6], c7 = sc[7], c8 = sc[8], c9 = sc[9];
    const float bias = sc[10];

    // Row 0 = {v0.xyzw, v1.xyzw, v2.xy}
    float r0 = v0.x * c0;
    r0 = fmaf(v0.y, c1, r0);
    r0 = fmaf(v0.z, c2, r0);
    r0 = fmaf(v0.w, c3, r0);
    r0 = fmaf(v1.x, c4, r0);
    r0 = fmaf(v1.y, c5, r0);
    r0 = fmaf(v1.z, c6, r0);
    r0 = fmaf(v1.w, c7, r0);
    r0 = fmaf(v2.x, c8, r0);
    r0 = fmaf(v2.y, c9, r0);

    // Row 1 = {v2.zw, v3.xyzw, v4.xyzw}
    float r1 = v2.z * c0;
    r1 = fmaf(v2.w, c1, r1);
    r1 = fmaf(v3.x, c2, r1);
    r1 = fmaf(v3.y, c3, r1);
    r1 = fmaf(v3.z, c4, r1);
    r1 = fmaf(v3.w, c5, r1);
    r1 = fmaf(v4.x, c6, r1);
    r1 = fmaf(v4.y, c7, r1);
    r1 = fmaf(v4.z, c8, r1);
    r1 = fmaf(v4.w, c9, r1);

    // ---- 4. predicated store (no early return: all threads hit the BAR) ----
    if (active) {
        __stcs(out2 + t, make_float2(r0 + bias, r1 + bias));
    }
}

extern "C" void kernel_launch(void* const* d_in, const int* in_sizes, int n_in,
                              void* d_out, int out_size) {
    const float* x = (const float*)d_in[0];   // [B, 10]
    const float* W = (const float*)d_in[1];   // [10, 1, 10]
    const float* b = (const float*)d_in[2];   // [10, 1]

    int B = in_sizes[0] / 10;                 // 4,000,000
    int npairs = B / 2;                       // B is even

    int threads = 256;
    int blocks = (npairs + threads - 1) / threads;
    forest_hidden_kernel<<<blocks, threads>>>(
        (const float4*)x, W, b, (float2*)d_out, npairs);
}